// round 2
// baseline (speedup 1.0000x reference)
#include <cuda_runtime.h>
#include <math.h>

// Problem constants
#define L_STEPS 128
#define NB 64
#define HID 4096            // 32*16*8
#define T1P 136             // padded row stride for t1 [32][136] (136 % 32 == 8 -> conflict-free mode-2 gather)
#define T2P 136             // padded row stride for t2 [32][136]

// XW scratch: (L, 3, N, 4096) fp32 = 402 MB. __device__ global = allowed scratch.
__device__ float g_xw[(size_t)L_STEPS * 3 * NB * HID];

// ---------------------------------------------------------------------------
// Stage 1: XW[l,g,n,d,e,f] = sum_{a,b,c} x[n,l,a,b,c] W1[g,d,a] W2[g,e,b] W3[g,f,c]
// One CTA per (n,l); 128 threads; 3 gates per CTA (x loaded once).
// ---------------------------------------------------------------------------
__global__ __launch_bounds__(128) void xw_kernel(
    const float* __restrict__ x,
    const float* __restrict__ W1,   // (3,32,32)
    const float* __restrict__ W2,   // (3,16,16)
    const float* __restrict__ W3)   // (3,8,8)
{
    extern __shared__ float sm[];
    float* xs = sm;                 // [32][128] : x[a][b*8+c]
    float* t1 = xs + 4096;          // [32][T1P]
    float* t2 = t1 + 32 * T1P;      // [32][T2P]
    float* w1 = t2 + 32 * T2P;      // 3*32*32
    float* w2 = w1 + 3072;          // 3*16*16
    float* w3 = w2 + 768;           // 3*8*8

    const int tid = threadIdx.x;
    const int n = blockIdx.x;
    const int l = blockIdx.y;

    const float* xg = x + ((size_t)n * L_STEPS + l) * HID;
    for (int i = tid; i < 4096; i += 128) xs[i] = xg[i];
    for (int i = tid; i < 3072; i += 128) w1[i] = W1[i];
    for (int i = tid; i < 768;  i += 128) w2[i] = W2[i];
    for (int i = tid; i < 192;  i += 128) w3[i] = W3[i];
    __syncthreads();

    // cache this thread's x column (bc = tid) once; reused across all 3 gates
    float xcol[32];
#pragma unroll
    for (int a = 0; a < 32; a++) xcol[a] = xs[a * 128 + tid];

    for (int g = 0; g < 3; g++) {
        // ---- mode-1: t1[d][bc] = sum_a W1[g,d,a] * x[a][bc] ----
        const float* w1g = w1 + g * 1024;
        for (int d0 = 0; d0 < 32; d0 += 4) {
            float a0 = 0.f, a1 = 0.f, a2 = 0.f, a3 = 0.f;
#pragma unroll
            for (int a = 0; a < 32; a++) {
                float xa = xcol[a];
                a0 += w1g[(d0 + 0) * 32 + a] * xa;
                a1 += w1g[(d0 + 1) * 32 + a] * xa;
                a2 += w1g[(d0 + 2) * 32 + a] * xa;
                a3 += w1g[(d0 + 3) * 32 + a] * xa;
            }
            t1[(d0 + 0) * T1P + tid] = a0;
            t1[(d0 + 1) * T1P + tid] = a1;
            t1[(d0 + 2) * T1P + tid] = a2;
            t1[(d0 + 3) * T1P + tid] = a3;
        }
        __syncthreads();

        // ---- mode-2: t2[d][e*8+c] = sum_b W2[g,e,b] * t1[d][b*8+c] ----
        const float* w2g = w2 + g * 256;
#pragma unroll
        for (int pp = 0; pp < 2; pp++) {
            int p = tid + pp * 128;       // (d,c) pair
            int d = p >> 3, c = p & 7;
            float col[16];
#pragma unroll
            for (int b = 0; b < 16; b++) col[b] = t1[d * T1P + b * 8 + c];
#pragma unroll 4
            for (int e = 0; e < 16; e++) {
                float acc = 0.f;
#pragma unroll
                for (int b = 0; b < 16; b++) acc += w2g[e * 16 + b] * col[b];
                t2[d * T2P + e * 8 + c] = acc;
            }
        }
        __syncthreads();

        // ---- mode-3: XW[d,e,f] = sum_c W3[g,f,c] * t2[d][e*8+c] ----
        const float* w3g = w3 + g * 64;
        float* outg = g_xw + (((size_t)l * 3 + g) * NB + n) * HID;
#pragma unroll
        for (int pp = 0; pp < 4; pp++) {
            int p = tid + pp * 128;       // (d,e) pair: d=p>>4, e=p&15
            int d = p >> 4, e = p & 15;
            float col[8];
#pragma unroll
            for (int c = 0; c < 8; c++) col[c] = t2[d * T2P + e * 8 + c];
#pragma unroll
            for (int f = 0; f < 8; f++) {
                float acc = 0.f;
#pragma unroll
                for (int c = 0; c < 8; c++) acc += w3g[f * 8 + c] * col[c];
                outg[p * 8 + f] = acc;
            }
        }
        __syncthreads();   // protect t1/t2 reuse for next gate
    }
}

// ---------------------------------------------------------------------------
// Stage 2: sequential GRU recurrence. One CTA per sample n (64 CTAs, 256 thr).
// h lives in SMEM for the whole kernel; no inter-CTA sync needed.
// ---------------------------------------------------------------------------
__global__ __launch_bounds__(256) void gru_kernel(
    const float* __restrict__ U1,   // (3,32,32)
    const float* __restrict__ U2,   // (3,16,16)
    const float* __restrict__ U3,   // (3,8,8)
    float* __restrict__ out)        // outs (N,L,4096) then h_last (N,4096)
{
    extern __shared__ float sm[];
    float* hs  = sm;                 // [32][128] h state
    float* t1  = hs + 4096;          // [32][T1P]
    float* t2  = t1 + 32 * T1P;      // [32][T2P]
    float* hub = t2 + 32 * T2P;      // 3 * 4096 (hu per gate)
    float* u1  = hub + 3 * 4096;     // 3072
    float* u2  = u1 + 3072;          // 768
    float* u3  = u2 + 768;           // 192

    const int t = threadIdx.x;
    const int n = blockIdx.x;

    for (int i = t; i < 4096; i += 256) hs[i] = 0.f;
    for (int i = t; i < 3072; i += 256) u1[i] = U1[i];
    for (int i = t; i < 768;  i += 256) u2[i] = U2[i];
    for (int i = t; i < 192;  i += 256) u3[i] = U3[i];
    __syncthreads();

    const int bc = t & 127;            // mode-1: column owned
    const int dbase = (t >> 7) * 16;   // mode-1: d half
    const int d2 = t >> 3, c2 = t & 7; // mode-2: (d,c) pair

    for (int l = 0; l < L_STEPS; l++) {
        for (int g = 0; g < 3; g++) {
            // ---- mode-1: t1[d][bc] = sum_a U1[g,d,a] * h[a][bc] ----
            const float* u1g = u1 + g * 1024;
            float hcol[32];
#pragma unroll
            for (int a = 0; a < 32; a++) hcol[a] = hs[a * 128 + bc];
            for (int d0 = dbase; d0 < dbase + 16; d0 += 4) {
                float a0 = 0.f, a1 = 0.f, a2 = 0.f, a3 = 0.f;
#pragma unroll
                for (int a = 0; a < 32; a++) {
                    float ha = hcol[a];
                    a0 += u1g[(d0 + 0) * 32 + a] * ha;
                    a1 += u1g[(d0 + 1) * 32 + a] * ha;
                    a2 += u1g[(d0 + 2) * 32 + a] * ha;
                    a3 += u1g[(d0 + 3) * 32 + a] * ha;
                }
                t1[(d0 + 0) * T1P + bc] = a0;
                t1[(d0 + 1) * T1P + bc] = a1;
                t1[(d0 + 2) * T1P + bc] = a2;
                t1[(d0 + 3) * T1P + bc] = a3;
            }
            __syncthreads();

            // ---- mode-2 ----
            const float* u2g = u2 + g * 256;
            {
                float col[16];
#pragma unroll
                for (int b = 0; b < 16; b++) col[b] = t1[d2 * T1P + b * 8 + c2];
#pragma unroll 4
                for (int e = 0; e < 16; e++) {
                    float acc = 0.f;
#pragma unroll
                    for (int b = 0; b < 16; b++) acc += u2g[e * 16 + b] * col[b];
                    t2[d2 * T2P + e * 8 + c2] = acc;
                }
            }
            __syncthreads();

            // ---- mode-3 -> hub[g] ----
            const float* u3g = u3 + g * 64;
            float* hug = hub + g * 4096;
#pragma unroll
            for (int pp = 0; pp < 2; pp++) {
                int p = t + pp * 256;      // (d,e) pair
                int d = p >> 4, e = p & 15;
                float col[8];
#pragma unroll
                for (int c = 0; c < 8; c++) col[c] = t2[d * T2P + e * 8 + c];
#pragma unroll
                for (int f = 0; f < 8; f++) {
                    float acc = 0.f;
#pragma unroll
                    for (int c = 0; c < 8; c++) acc += u3g[f * 8 + c] * col[c];
                    hug[p * 8 + f] = acc;
                }
            }
            __syncthreads();
        }

        // ---- gate combine + state update + output write ----
        const float* xw0 = g_xw + (((size_t)l * 3 + 0) * NB + n) * HID;
        const float* xw1 = g_xw + (((size_t)l * 3 + 1) * NB + n) * HID;
        const float* xw2 = g_xw + (((size_t)l * 3 + 2) * NB + n) * HID;
        float* outl = out + ((size_t)n * L_STEPS + l) * HID;
        for (int i = t; i < 4096; i += 256) {
            float z  = 1.f / (1.f + __expf(-(xw0[i] + hub[i])));
            float r  = 1.f / (1.f + __expf(-(xw1[i] + hub[4096 + i])));
            float hh = tanhf(xw2[i] + r * hub[8192 + i]);
            float hn = z * hs[i] + (1.f - z) * hh;
            hs[i] = hn;
            outl[i] = hn;
        }
        __syncthreads();
    }

    // h_last
    float* hl = out + (size_t)NB * L_STEPS * HID + (size_t)n * HID;
    for (int i = t; i < 4096; i += 256) hl[i] = hs[i];
}

// ---------------------------------------------------------------------------
extern "C" void kernel_launch(void* const* d_in, const int* in_sizes, int n_in,
                              void* d_out, int out_size)
{
    const float* x  = (const float*)d_in[0];
    const float* W1 = (const float*)d_in[1];
    const float* W2 = (const float*)d_in[2];
    const float* W3 = (const float*)d_in[3];
    const float* U1 = (const float*)d_in[4];
    const float* U2 = (const float*)d_in[5];
    const float* U3 = (const float*)d_in[6];
    float* out = (float*)d_out;

    const int SMEM1 = (4096 + 32 * T1P + 32 * T2P + 3072 + 768 + 192) * (int)sizeof(float);
    const int SMEM2 = (4096 + 32 * T1P + 32 * T2P + 3 * 4096 + 3072 + 768 + 192) * (int)sizeof(float);

    cudaFuncSetAttribute(xw_kernel,  cudaFuncAttributeMaxDynamicSharedMemorySize, SMEM1);
    cudaFuncSetAttribute(gru_kernel, cudaFuncAttributeMaxDynamicSharedMemorySize, SMEM2);

    dim3 grid1(NB, L_STEPS);
    xw_kernel<<<grid1, 128, SMEM1>>>(x, W1, W2, W3);
    gru_kernel<<<NB, 256, SMEM2>>>(U1, U2, U3, out);
}

// round 3
// speedup vs baseline: 3.1043x; 3.1043x over previous
#include <cuda_runtime.h>
#include <math.h>

// Problem constants
#define L_STEPS 128
#define NB 64
#define HID 4096            // 32*16*8
#define T1P 136             // padded t1 row stride (conflict-free mode-2 reads)

// XW scratch: (L, 3, N, 4096) fp32 = 402 MB. __device__ global = allowed scratch.
__device__ float g_xw[(size_t)L_STEPS * 3 * NB * HID];

// ---------------------------------------------------------------------------
// Stage 1: XW[l,g,n,d,e,f] = sum_{a,b,c} x[n,l,a,b,c] W1[g,d,a] W2[g,e,b] W3[g,f,c]
// One CTA per (n,l); 128 threads; 3 gates per CTA. (unchanged from R2)
// ---------------------------------------------------------------------------
__global__ __launch_bounds__(128) void xw_kernel(
    const float* __restrict__ x,
    const float* __restrict__ W1,   // (3,32,32)
    const float* __restrict__ W2,   // (3,16,16)
    const float* __restrict__ W3)   // (3,8,8)
{
    extern __shared__ float sm[];
    float* xs = sm;                 // [32][128]
    float* t1 = xs + 4096;          // [32][T1P]
    float* t2 = t1 + 32 * T1P;      // [32][T1P]
    float* w1 = t2 + 32 * T1P;      // 3*32*32
    float* w2 = w1 + 3072;          // 3*16*16
    float* w3 = w2 + 768;           // 3*8*8

    const int tid = threadIdx.x;
    const int n = blockIdx.x;
    const int l = blockIdx.y;

    const float* xg = x + ((size_t)n * L_STEPS + l) * HID;
    for (int i = tid; i < 4096; i += 128) xs[i] = xg[i];
    for (int i = tid; i < 3072; i += 128) w1[i] = W1[i];
    for (int i = tid; i < 768;  i += 128) w2[i] = W2[i];
    for (int i = tid; i < 192;  i += 128) w3[i] = W3[i];
    __syncthreads();

    float xcol[32];
#pragma unroll
    for (int a = 0; a < 32; a++) xcol[a] = xs[a * 128 + tid];

    for (int g = 0; g < 3; g++) {
        const float* w1g = w1 + g * 1024;
        for (int d0 = 0; d0 < 32; d0 += 4) {
            float a0 = 0.f, a1 = 0.f, a2 = 0.f, a3 = 0.f;
#pragma unroll
            for (int a = 0; a < 32; a++) {
                float xa = xcol[a];
                a0 += w1g[(d0 + 0) * 32 + a] * xa;
                a1 += w1g[(d0 + 1) * 32 + a] * xa;
                a2 += w1g[(d0 + 2) * 32 + a] * xa;
                a3 += w1g[(d0 + 3) * 32 + a] * xa;
            }
            t1[(d0 + 0) * T1P + tid] = a0;
            t1[(d0 + 1) * T1P + tid] = a1;
            t1[(d0 + 2) * T1P + tid] = a2;
            t1[(d0 + 3) * T1P + tid] = a3;
        }
        __syncthreads();

        const float* w2g = w2 + g * 256;
#pragma unroll
        for (int pp = 0; pp < 2; pp++) {
            int p = tid + pp * 128;       // (d,c)
            int d = p >> 3, c = p & 7;
            float col[16];
#pragma unroll
            for (int b = 0; b < 16; b++) col[b] = t1[d * T1P + b * 8 + c];
#pragma unroll 4
            for (int e = 0; e < 16; e++) {
                float acc = 0.f;
#pragma unroll
                for (int b = 0; b < 16; b++) acc += w2g[e * 16 + b] * col[b];
                t2[d * T1P + e * 8 + c] = acc;
            }
        }
        __syncthreads();

        const float* w3g = w3 + g * 64;
        float* outg = g_xw + (((size_t)l * 3 + g) * NB + n) * HID;
#pragma unroll
        for (int pp = 0; pp < 4; pp++) {
            int p = tid + pp * 128;       // (d,e)
            int d = p >> 4, e = p & 15;
            float col[8];
#pragma unroll
            for (int c = 0; c < 8; c++) col[c] = t2[d * T1P + e * 8 + c];
#pragma unroll
            for (int f = 0; f < 8; f++) {
                float acc = 0.f;
#pragma unroll
                for (int c = 0; c < 8; c++) acc += w3g[f * 8 + c] * col[c];
                outg[p * 8 + f] = acc;
            }
        }
        __syncthreads();
    }
}

// ---------------------------------------------------------------------------
// Stage 2: sequential GRU recurrence. One CTA per sample n; 512 threads.
// SMEM (floats): hs 4096 | t1 3*32*136 | t2 3*32*144 | u1t 32*96 | w2t 768 | u3 192
// ---------------------------------------------------------------------------
#define T2DS 144   // t2 per-d stride (words);  element (g,d,e,c) -> g*4608 + d*144 + e*9 + c
#define U1TS 96    // u1t row stride: u1t[a*96 + (g*32+d)] = U1[g,d,a]

__global__ __launch_bounds__(512) void gru_kernel(
    const float* __restrict__ U1,   // (3,32,32)
    const float* __restrict__ U2,   // (3,16,16)
    const float* __restrict__ U3,   // (3,8,8)
    float* __restrict__ out)        // outs (N,L,4096) then h_last (N,4096)
{
    extern __shared__ float sm[];
    float* hs  = sm;                   // 4096
    float* t1  = hs + 4096;            // 13056
    float* t2  = t1 + 3 * 32 * T1P;    // 13824
    float* u1t = t2 + 3 * 32 * T2DS;   // 3072
    float* w2t = u1t + 32 * U1TS;      // 768: w2t[g*256 + b*16 + e] = U2[g,e,b]
    float* u3s = w2t + 768;            // 192

    const int t    = threadIdx.x;
    const int n    = blockIdx.x;
    const int lane = t & 31;
    const int warp = t >> 5;

    for (int i = t; i < 4096; i += 512) hs[i] = 0.f;
    for (int i = t; i < 3072; i += 512) {
        int g = i >> 10, rem = i & 1023, d = rem >> 5, a = rem & 31;
        u1t[a * U1TS + g * 32 + d] = U1[i];
    }
    for (int i = t; i < 768; i += 512) {
        int g = i >> 8, rem = i & 255, e = rem >> 4, b = rem & 15;
        w2t[g * 256 + b * 16 + e] = U2[i];
    }
    for (int i = t; i < 192; i += 512) u3s[i] = U3[i];
    __syncthreads();

    // phase-1 mapping: warp -> rows r0..r0+5 (r = g*32+d), lane -> cols bc0..bc0+3
    const int r0  = warp * 6;
    const int bc0 = lane * 4;
    // phase-2 mapping: per gate, thread -> (d2, e0..e0+3, c0..c0+1)
    const int d2 = t >> 4;
    const int e0 = ((t >> 2) & 3) * 4;
    const int c0 = (t & 3) * 2;
    // phase-3 mapping: thread = pair p = (d,e); owns elements p*8 .. p*8+7
    const int p  = t;

    for (int l = 0; l < L_STEPS; l++) {
        // ---------------- phase 1: mode-1  t1[r][bc] = sum_a u1t[a][r]*h[a][bc]
        float acc[6][4];
#pragma unroll
        for (int j = 0; j < 6; j++)
#pragma unroll
            for (int k = 0; k < 4; k++) acc[j][k] = 0.f;

#pragma unroll
        for (int a = 0; a < 32; a++) {
            float4 h4 = *reinterpret_cast<const float4*>(&hs[a * 128 + bc0]);
            float2 wa = *reinterpret_cast<const float2*>(&u1t[a * U1TS + r0]);
            float2 wb = *reinterpret_cast<const float2*>(&u1t[a * U1TS + r0 + 2]);
            float2 wc = *reinterpret_cast<const float2*>(&u1t[a * U1TS + r0 + 4]);
            float w[6] = {wa.x, wa.y, wb.x, wb.y, wc.x, wc.y};
#pragma unroll
            for (int j = 0; j < 6; j++) {
                acc[j][0] += w[j] * h4.x;
                acc[j][1] += w[j] * h4.y;
                acc[j][2] += w[j] * h4.z;
                acc[j][3] += w[j] * h4.w;
            }
        }
#pragma unroll
        for (int j = 0; j < 6; j++)
            *reinterpret_cast<float4*>(&t1[(r0 + j) * T1P + bc0]) =
                make_float4(acc[j][0], acc[j][1], acc[j][2], acc[j][3]);

        // prefetch this step's XW (consumed in phase 3) — hides DRAM behind phase 2
        float4 xf[6];
#pragma unroll
        for (int g = 0; g < 3; g++) {
            const float4* src = reinterpret_cast<const float4*>(
                g_xw + (((size_t)l * 3 + g) * NB + n) * HID + p * 8);
            xf[g * 2]     = src[0];
            xf[g * 2 + 1] = src[1];
        }
        __syncthreads();

        // ---------------- phase 2: mode-2  t2[g,d,e,c] = sum_b U2[g,e,b]*t1[g,d,b*8+c]
#pragma unroll
        for (int g = 0; g < 3; g++) {
            const float* t1g = t1 + g * (32 * T1P) + d2 * T1P;
            const float* w2g = w2t + g * 256;
            float a00 = 0.f, a01 = 0.f, a10 = 0.f, a11 = 0.f;
            float a20 = 0.f, a21 = 0.f, a30 = 0.f, a31 = 0.f;
#pragma unroll
            for (int b = 0; b < 16; b++) {
                float2 tv = *reinterpret_cast<const float2*>(&t1g[b * 8 + c0]);
                float4 wv = *reinterpret_cast<const float4*>(&w2g[b * 16 + e0]);
                a00 += wv.x * tv.x;  a01 += wv.x * tv.y;
                a10 += wv.y * tv.x;  a11 += wv.y * tv.y;
                a20 += wv.z * tv.x;  a21 += wv.z * tv.y;
                a30 += wv.w * tv.x;  a31 += wv.w * tv.y;
            }
            float* t2g = t2 + g * (32 * T2DS) + d2 * T2DS;
            t2g[(e0 + 0) * 9 + c0]     = a00;  t2g[(e0 + 0) * 9 + c0 + 1] = a01;
            t2g[(e0 + 1) * 9 + c0]     = a10;  t2g[(e0 + 1) * 9 + c0 + 1] = a11;
            t2g[(e0 + 2) * 9 + c0]     = a20;  t2g[(e0 + 2) * 9 + c0 + 1] = a21;
            t2g[(e0 + 3) * 9 + c0]     = a30;  t2g[(e0 + 3) * 9 + c0 + 1] = a31;
        }
        __syncthreads();

        // ---------------- phase 3: mode-3 + gate combine (elements p*8..p*8+7)
        float hu[3][8];
#pragma unroll
        for (int g = 0; g < 3; g++) {
            const float* t2g = t2 + g * (32 * T2DS) + (p >> 4) * T2DS + (p & 15) * 9;
            float col[8];
#pragma unroll
            for (int c = 0; c < 8; c++) col[c] = t2g[c];
            const float* u3g = u3s + g * 64;
#pragma unroll
            for (int f = 0; f < 8; f++) {
                float4 ua = *reinterpret_cast<const float4*>(&u3g[f * 8]);
                float4 ub = *reinterpret_cast<const float4*>(&u3g[f * 8 + 4]);
                hu[g][f] = ua.x * col[0] + ua.y * col[1] + ua.z * col[2] + ua.w * col[3]
                         + ub.x * col[4] + ub.y * col[5] + ub.z * col[6] + ub.w * col[7];
            }
        }
        // unpack xw prefetch
        float xg0[8], xg1[8], xg2[8];
        xg0[0]=xf[0].x; xg0[1]=xf[0].y; xg0[2]=xf[0].z; xg0[3]=xf[0].w;
        xg0[4]=xf[1].x; xg0[5]=xf[1].y; xg0[6]=xf[1].z; xg0[7]=xf[1].w;
        xg1[0]=xf[2].x; xg1[1]=xf[2].y; xg1[2]=xf[2].z; xg1[3]=xf[2].w;
        xg1[4]=xf[3].x; xg1[5]=xf[3].y; xg1[6]=xf[3].z; xg1[7]=xf[3].w;
        xg2[0]=xf[4].x; xg2[1]=xf[4].y; xg2[2]=xf[4].z; xg2[3]=xf[4].w;
        xg2[4]=xf[5].x; xg2[5]=xf[5].y; xg2[6]=xf[5].z; xg2[7]=xf[5].w;

        float4 ho0 = *reinterpret_cast<const float4*>(&hs[p * 8]);
        float4 ho1 = *reinterpret_cast<const float4*>(&hs[p * 8 + 4]);
        float hold[8] = {ho0.x, ho0.y, ho0.z, ho0.w, ho1.x, ho1.y, ho1.z, ho1.w};

        float res[8];
#pragma unroll
        for (int f = 0; f < 8; f++) {
            float z  = 1.f / (1.f + __expf(-(xg0[f] + hu[0][f])));
            float r  = 1.f / (1.f + __expf(-(xg1[f] + hu[1][f])));
            float ax = xg2[f] + r * hu[2][f];
            float e2 = __expf(2.f * ax);
            float hh = 1.f - 2.f / (e2 + 1.f);      // tanh, NaN-safe at +/-inf
            res[f] = z * hold[f] + (1.f - z) * hh;
        }
        *reinterpret_cast<float4*>(&hs[p * 8])     = make_float4(res[0], res[1], res[2], res[3]);
        *reinterpret_cast<float4*>(&hs[p * 8 + 4]) = make_float4(res[4], res[5], res[6], res[7]);

        float* outl = out + ((size_t)n * L_STEPS + l) * HID + p * 8;
        *reinterpret_cast<float4*>(outl)     = make_float4(res[0], res[1], res[2], res[3]);
        *reinterpret_cast<float4*>(outl + 4) = make_float4(res[4], res[5], res[6], res[7]);
        __syncthreads();
    }

    // h_last
    float* hl = out + (size_t)NB * L_STEPS * HID + (size_t)n * HID;
    for (int i = t; i < 4096; i += 512) hl[i] = hs[i];
}

// ---------------------------------------------------------------------------
extern "C" void kernel_launch(void* const* d_in, const int* in_sizes, int n_in,
                              void* d_out, int out_size)
{
    const float* x  = (const float*)d_in[0];
    const float* W1 = (const float*)d_in[1];
    const float* W2 = (const float*)d_in[2];
    const float* W3 = (const float*)d_in[3];
    const float* U1 = (const float*)d_in[4];
    const float* U2 = (const float*)d_in[5];
    const float* U3 = (const float*)d_in[6];
    float* out = (float*)d_out;

    const int SMEM1 = (4096 + 32 * T1P + 32 * T1P + 3072 + 768 + 192) * (int)sizeof(float);
    const int SMEM2 = (4096 + 3 * 32 * T1P + 3 * 32 * T2DS + 32 * U1TS + 768 + 192) * (int)sizeof(float);

    cudaFuncSetAttribute(xw_kernel,  cudaFuncAttributeMaxDynamicSharedMemorySize, SMEM1);
    cudaFuncSetAttribute(gru_kernel, cudaFuncAttributeMaxDynamicSharedMemorySize, SMEM2);

    dim3 grid1(NB, L_STEPS);
    xw_kernel<<<grid1, 128, SMEM1>>>(x, W1, W2, W3);
    gru_kernel<<<NB, 512, SMEM2>>>(U1, U2, U3, out);
}

// round 4
// speedup vs baseline: 3.5635x; 1.1479x over previous
#include <cuda_runtime.h>
#include <math.h>
#include <cstdint>

// Problem constants
#define L_STEPS 128
#define NB 64
#define HID 4096            // 32*16*8
#define T1P 136             // padded t1 row stride
#define T2DS 144            // t2 per-row stride; (e,c) -> e*9 + c

// XW scratch: (L, 3, N, 4096) fp32 = 402 MB.
__device__ float g_xw[(size_t)L_STEPS * 3 * NB * HID];

__device__ __forceinline__ uint32_t smem_u32(const void* p) {
    uint32_t a;
    asm("{ .reg .u64 t; cvta.to.shared.u64 t, %1; cvt.u32.u64 %0, t; }" : "=r"(a) : "l"(p));
    return a;
}
__device__ __forceinline__ uint32_t mapa_u32(uint32_t addr, uint32_t rank) {
    uint32_t r;
    asm("mapa.shared::cluster.u32 %0, %1, %2;" : "=r"(r) : "r"(addr), "r"(rank));
    return r;
}
__device__ __forceinline__ void st_cluster_f32(uint32_t addr, float v) {
    asm volatile("st.shared::cluster.b32 [%0], %1;" :: "r"(addr), "r"(__float_as_uint(v)) : "memory");
}

// ---------------------------------------------------------------------------
// Stage 1: XW[l,g,n,:] = x[n,l,:] x1 W1[g] x2 W2[g] x3 W3[g]
// One CTA per (n,l); 512 threads; gates processed sequentially (t1/t2 reused).
// ---------------------------------------------------------------------------
__global__ __launch_bounds__(512) void xw_kernel(
    const float* __restrict__ x,
    const float* __restrict__ W1,   // (3,32,32)
    const float* __restrict__ W2,   // (3,16,16)
    const float* __restrict__ W3)   // (3,8,8)
{
    extern __shared__ float sm[];
    float* xs  = sm;              // 4096                x[a][b*8+c]
    float* t1  = xs + 4096;       // 32*T1P = 4352
    float* t2  = t1 + 4352;       // 32*T2DS = 4608
    float* w1t = t2 + 4608;       // 3072: w1t[a*96 + g*32 + d] = W1[g,d,a]
    float* w2t = w1t + 3072;      // 768:  w2t[g*256 + b*16 + e] = W2[g,e,b]
    float* w3s = w2t + 768;       // 192

    const int t = threadIdx.x;
    const int n = blockIdx.x;
    const int l = blockIdx.y;

    {
        const float4* xg4 = reinterpret_cast<const float4*>(x + ((size_t)n * L_STEPS + l) * HID);
        float4* xs4 = reinterpret_cast<float4*>(xs);
        for (int i = t; i < 1024; i += 512) xs4[i] = xg4[i];
    }
    for (int i = t; i < 3072; i += 512) {
        int g = i >> 10, rem = i & 1023, d = rem >> 5, a = rem & 31;
        w1t[a * 96 + g * 32 + d] = W1[i];
    }
    for (int i = t; i < 768; i += 512) {
        int g = i >> 8, rem = i & 255, e = rem >> 4, b = rem & 15;
        w2t[g * 256 + b * 16 + e] = W2[i];
    }
    for (int i = t; i < 192; i += 512) w3s[i] = W3[i];
    __syncthreads();

    const int warp = t >> 5, lane = t & 31;
    // phase1: warp -> 4 d-rows, lane -> 2 cols
    const int d0  = (warp & 7) * 4;
    const int bc0 = (warp >> 3) * 64 + lane * 2;
    // phase2: thread -> (d, e0..e0+3, c0..c0+1)
    const int dP2 = t >> 4;
    const int e0  = ((t >> 2) & 3) * 4;
    const int c0  = (t & 3) * 2;
    // phase3: thread = (d,e) pair
    const int p = t;

    for (int g = 0; g < 3; g++) {
        // ---- mode-1: t1[d][bc] = sum_a W1[g,d,a] * x[a][bc] ----
        float acc[4][2];
#pragma unroll
        for (int j = 0; j < 4; j++) { acc[j][0] = 0.f; acc[j][1] = 0.f; }
#pragma unroll
        for (int a = 0; a < 32; a++) {
            float2 x2 = *reinterpret_cast<const float2*>(&xs[a * 128 + bc0]);
            float4 wv = *reinterpret_cast<const float4*>(&w1t[a * 96 + g * 32 + d0]);
            acc[0][0] += wv.x * x2.x;  acc[0][1] += wv.x * x2.y;
            acc[1][0] += wv.y * x2.x;  acc[1][1] += wv.y * x2.y;
            acc[2][0] += wv.z * x2.x;  acc[2][1] += wv.z * x2.y;
            acc[3][0] += wv.w * x2.x;  acc[3][1] += wv.w * x2.y;
        }
#pragma unroll
        for (int j = 0; j < 4; j++)
            *reinterpret_cast<float2*>(&t1[(d0 + j) * T1P + bc0]) =
                make_float2(acc[j][0], acc[j][1]);
        __syncthreads();

        // ---- mode-2: t2[d][e*9+c] = sum_b W2[g,e,b] * t1[d][b*8+c] ----
        {
            const float* t1d = t1 + dP2 * T1P;
            const float* w2g = w2t + g * 256;
            float a00 = 0.f, a01 = 0.f, a10 = 0.f, a11 = 0.f;
            float a20 = 0.f, a21 = 0.f, a30 = 0.f, a31 = 0.f;
#pragma unroll
            for (int b = 0; b < 16; b++) {
                float2 tv = *reinterpret_cast<const float2*>(&t1d[b * 8 + c0]);
                float4 wv = *reinterpret_cast<const float4*>(&w2g[b * 16 + e0]);
                a00 += wv.x * tv.x;  a01 += wv.x * tv.y;
                a10 += wv.y * tv.x;  a11 += wv.y * tv.y;
                a20 += wv.z * tv.x;  a21 += wv.z * tv.y;
                a30 += wv.w * tv.x;  a31 += wv.w * tv.y;
            }
            float* t2d = t2 + dP2 * T2DS;
            t2d[(e0 + 0) * 9 + c0] = a00;  t2d[(e0 + 0) * 9 + c0 + 1] = a01;
            t2d[(e0 + 1) * 9 + c0] = a10;  t2d[(e0 + 1) * 9 + c0 + 1] = a11;
            t2d[(e0 + 2) * 9 + c0] = a20;  t2d[(e0 + 2) * 9 + c0 + 1] = a21;
            t2d[(e0 + 3) * 9 + c0] = a30;  t2d[(e0 + 3) * 9 + c0 + 1] = a31;
        }
        __syncthreads();

        // ---- mode-3: out[p*8+f] = sum_c W3[g,f,c] * t2[d][e*9+c] ----
        {
            const float* t2c = t2 + (p >> 4) * T2DS + (p & 15) * 9;
            float col[8];
#pragma unroll
            for (int c = 0; c < 8; c++) col[c] = t2c[c];
            const float* w3g = w3s + g * 64;
            float o[8];
#pragma unroll
            for (int f = 0; f < 8; f++) {
                float4 ua = *reinterpret_cast<const float4*>(&w3g[f * 8]);
                float4 ub = *reinterpret_cast<const float4*>(&w3g[f * 8 + 4]);
                o[f] = ua.x * col[0] + ua.y * col[1] + ua.z * col[2] + ua.w * col[3]
                     + ub.x * col[4] + ub.y * col[5] + ub.z * col[6] + ub.w * col[7];
            }
            float* outg = g_xw + (((size_t)l * 3 + g) * NB + n) * HID + p * 8;
            *reinterpret_cast<float4*>(outg)     = make_float4(o[0], o[1], o[2], o[3]);
            *reinterpret_cast<float4*>(outg + 4) = make_float4(o[4], o[5], o[6], o[7]);
        }
        __syncthreads();   // protect t1/t2 for next gate
    }
}

// ---------------------------------------------------------------------------
// Stage 2: GRU recurrence. Cluster of 2 CTAs per sample (128 CTAs, 512 thr).
// Each CTA owns d in [rank*16, rank*16+16); full h replicated & double-buffered;
// halves exchanged via DSMEM each step; ONE cluster barrier per step.
// ---------------------------------------------------------------------------
__global__ __launch_bounds__(512) __cluster_dims__(2, 1, 1)
void gru_kernel(
    const float* __restrict__ U1,   // (3,32,32)
    const float* __restrict__ U2,   // (3,16,16)
    const float* __restrict__ U3,   // (3,8,8)
    float* __restrict__ out)        // outs (N,L,4096) then h_last (N,4096)
{
    extern __shared__ float sm[];
    float* h0  = sm;                 // 4096
    float* h1  = h0 + 4096;          // 4096
    float* t1  = h1 + 4096;          // 48*T1P = 6528   rows r = g*16+dd
    float* t2  = t1 + 6528;          // 48*T2DS = 6912
    float* u1t = t2 + 6912;          // 1536: u1t[a*48 + g*16 + dd] = U1[g, rank*16+dd, a]
    float* w2t = u1t + 1536;         // 768:  w2t[g*256 + b*16 + e] = U2[g,e,b]
    float* u3s = w2t + 768;          // 192

    const int t    = threadIdx.x;
    const int n    = blockIdx.x >> 1;
    const int rank = blockIdx.x & 1;
    const int peer = rank ^ 1;

    for (int i = t; i < 4096; i += 512) h0[i] = 0.f;
    for (int i = t; i < 1536; i += 512) {
        int g = i >> 9, rem = i & 511, dd = rem >> 5, a = rem & 31;
        u1t[a * 48 + g * 16 + dd] = U1[((g * 32) + rank * 16 + dd) * 32 + a];
    }
    for (int i = t; i < 768; i += 512) {
        int g = i >> 8, rem = i & 255, e = rem >> 4, b = rem & 15;
        w2t[g * 256 + b * 16 + e] = U2[i];
    }
    for (int i = t; i < 192; i += 512) u3s[i] = U3[i];
    __syncthreads();

    const uint32_t h0a = smem_u32(h0);
    const uint32_t h1a = smem_u32(h1);

    const int warp = t >> 5, lane = t & 31;
    // phase1: warp -> 3 t1-rows (of 48), lane -> 4 cols
    const int r0  = warp * 3;
    const int bc0 = lane * 4;
    // phase2: thread -> (dd, e0..e0+3, single c)
    const int d2 = t >> 5;
    const int e0 = ((t >> 3) & 3) * 4;
    const int c1 = t & 7;
    // phase3: q = (dd,e) pair of this CTA's half; f0 = 4-element f group
    const int q   = t & 255;
    const int dd3 = q >> 4, e3 = q & 15;
    const int f0  = (t >> 8) * 4;
    const int gbase = ((rank * 16 + dd3) * 16 + e3) * 8 + f0;  // global hidden idx (4 elems)

    float* hc = h0;
    float* hn = h1;

    for (int l = 0; l < L_STEPS; l++) {
        // ---------- phase 1: t1[r][bc] = sum_a u1t[a][r] * hc[a*128+bc]
        float acc[3][4];
#pragma unroll
        for (int j = 0; j < 3; j++)
#pragma unroll
            for (int k = 0; k < 4; k++) acc[j][k] = 0.f;
#pragma unroll
        for (int a = 0; a < 32; a++) {
            float4 h4 = *reinterpret_cast<const float4*>(&hc[a * 128 + bc0]);
            float w0 = u1t[a * 48 + r0];
            float w1 = u1t[a * 48 + r0 + 1];
            float w2 = u1t[a * 48 + r0 + 2];
            acc[0][0] += w0 * h4.x; acc[0][1] += w0 * h4.y; acc[0][2] += w0 * h4.z; acc[0][3] += w0 * h4.w;
            acc[1][0] += w1 * h4.x; acc[1][1] += w1 * h4.y; acc[1][2] += w1 * h4.z; acc[1][3] += w1 * h4.w;
            acc[2][0] += w2 * h4.x; acc[2][1] += w2 * h4.y; acc[2][2] += w2 * h4.z; acc[2][3] += w2 * h4.w;
        }
#pragma unroll
        for (int j = 0; j < 3; j++)
            *reinterpret_cast<float4*>(&t1[(r0 + j) * T1P + bc0]) =
                make_float4(acc[j][0], acc[j][1], acc[j][2], acc[j][3]);

        // prefetch this step's XW (consumed in phase 3)
        float4 xf[3];
#pragma unroll
        for (int g = 0; g < 3; g++)
            xf[g] = *reinterpret_cast<const float4*>(
                g_xw + (((size_t)l * 3 + g) * NB + n) * HID + gbase);
        __syncthreads();

        // ---------- phase 2: t2[g,dd][e*9+c] = sum_b U2[g,e,b]*t1[g,dd][b*8+c]
#pragma unroll
        for (int g = 0; g < 3; g++) {
            const float* t1r = t1 + (g * 16 + d2) * T1P;
            const float* w2g = w2t + g * 256;
            float b0 = 0.f, b1 = 0.f, b2 = 0.f, b3 = 0.f;
#pragma unroll
            for (int b = 0; b < 16; b++) {
                float tv = t1r[b * 8 + c1];
                float4 wv = *reinterpret_cast<const float4*>(&w2g[b * 16 + e0]);
                b0 += wv.x * tv; b1 += wv.y * tv; b2 += wv.z * tv; b3 += wv.w * tv;
            }
            float* t2r = t2 + (g * 16 + d2) * T2DS;
            t2r[(e0 + 0) * 9 + c1] = b0;
            t2r[(e0 + 1) * 9 + c1] = b1;
            t2r[(e0 + 2) * 9 + c1] = b2;
            t2r[(e0 + 3) * 9 + c1] = b3;
        }
        __syncthreads();

        // ---------- phase 3: mode-3 + gate combine for 4 elements (gbase..+3)
        float hu[3][4];
#pragma unroll
        for (int g = 0; g < 3; g++) {
            const float* t2c = t2 + (g * 16 + dd3) * T2DS + e3 * 9;
            float col[8];
#pragma unroll
            for (int c = 0; c < 8; c++) col[c] = t2c[c];
            const float* u3g = u3s + g * 64;
#pragma unroll
            for (int j = 0; j < 4; j++) {
                float4 ua = *reinterpret_cast<const float4*>(&u3g[(f0 + j) * 8]);
                float4 ub = *reinterpret_cast<const float4*>(&u3g[(f0 + j) * 8 + 4]);
                hu[g][j] = ua.x * col[0] + ua.y * col[1] + ua.z * col[2] + ua.w * col[3]
                         + ub.x * col[4] + ub.y * col[5] + ub.z * col[6] + ub.w * col[7];
            }
        }
        float4 ho = *reinterpret_cast<const float4*>(&hc[gbase]);
        float hold[4] = {ho.x, ho.y, ho.z, ho.w};
        float xz[4] = {xf[0].x, xf[0].y, xf[0].z, xf[0].w};
        float xr[4] = {xf[1].x, xf[1].y, xf[1].z, xf[1].w};
        float xh[4] = {xf[2].x, xf[2].y, xf[2].z, xf[2].w};

        float res[4];
#pragma unroll
        for (int j = 0; j < 4; j++) {
            float z  = 1.f / (1.f + __expf(-(xz[j] + hu[0][j])));
            float r  = 1.f / (1.f + __expf(-(xr[j] + hu[1][j])));
            float ax = xh[j] + r * hu[2][j];
            float e2 = __expf(2.f * ax);
            float hh = 1.f - 2.f / (e2 + 1.f);
            res[j] = z * hold[j] + (1.f - z) * hh;
        }
        float4 r4 = make_float4(res[0], res[1], res[2], res[3]);
        *reinterpret_cast<float4*>(&hn[gbase]) = r4;

        // publish our half to peer's hn via DSMEM
        {
            uint32_t hna = (l & 1) ? h0a : h1a;       // address of hn buffer
            uint32_t ra = mapa_u32(hna + (uint32_t)gbase * 4u, (uint32_t)peer);
            st_cluster_f32(ra,      res[0]);
            st_cluster_f32(ra + 4,  res[1]);
            st_cluster_f32(ra + 8,  res[2]);
            st_cluster_f32(ra + 12, res[3]);
        }

        *reinterpret_cast<float4*>(out + ((size_t)n * L_STEPS + l) * HID + gbase) = r4;

        // one cluster barrier per step: peer's writes to hn become visible,
        // and nobody races ahead to overwrite the buffer we just read.
        asm volatile("barrier.cluster.arrive.aligned;" ::: "memory");
        asm volatile("barrier.cluster.wait.aligned;"   ::: "memory");

        float* tmp = hc; hc = hn; hn = tmp;
    }

    // h_last: each CTA writes its own half
    float* hl = out + (size_t)NB * L_STEPS * HID + (size_t)n * HID + rank * 2048;
    const float* hsrc = hc + rank * 2048;
    for (int i = t; i < 2048; i += 512) hl[i] = hsrc[i];
}

// ---------------------------------------------------------------------------
extern "C" void kernel_launch(void* const* d_in, const int* in_sizes, int n_in,
                              void* d_out, int out_size)
{
    const float* x  = (const float*)d_in[0];
    const float* W1 = (const float*)d_in[1];
    const float* W2 = (const float*)d_in[2];
    const float* W3 = (const float*)d_in[3];
    const float* U1 = (const float*)d_in[4];
    const float* U2 = (const float*)d_in[5];
    const float* U3 = (const float*)d_in[6];
    float* out = (float*)d_out;

    const int SMEM1 = (4096 + 4352 + 4608 + 3072 + 768 + 192) * (int)sizeof(float);
    const int SMEM2 = (4096 * 2 + 6528 + 6912 + 1536 + 768 + 192) * (int)sizeof(float);

    cudaFuncSetAttribute(xw_kernel,  cudaFuncAttributeMaxDynamicSharedMemorySize, SMEM1);
    cudaFuncSetAttribute(gru_kernel, cudaFuncAttributeMaxDynamicSharedMemorySize, SMEM2);

    dim3 grid1(NB, L_STEPS);
    xw_kernel<<<grid1, 512, SMEM1>>>(x, W1, W2, W3);
    gru_kernel<<<NB * 2, 512, SMEM2>>>(U1, U2, U3, out);
}

// round 5
// speedup vs baseline: 3.5766x; 1.0037x over previous
#include <cuda_runtime.h>
#include <math.h>
#include <cstdint>

// Problem constants
#define L_STEPS 128
#define NB 64
#define HID 4096            // 32*16*8
#define T1P 136             // padded t1 row stride
#define T2DS 144            // t2 per-row stride; (e,c) -> e*9 + c

// XW scratch: (L, 3, N, 4096) fp32 = 402 MB.
__device__ float g_xw[(size_t)L_STEPS * 3 * NB * HID];

__device__ __forceinline__ uint32_t smem_u32(const void* p) {
    uint32_t a;
    asm("{ .reg .u64 t; cvta.to.shared.u64 t, %1; cvt.u32.u64 %0, t; }" : "=r"(a) : "l"(p));
    return a;
}
__device__ __forceinline__ uint32_t mapa_u32(uint32_t addr, uint32_t rank) {
    uint32_t r;
    asm("mapa.shared::cluster.u32 %0, %1, %2;" : "=r"(r) : "r"(addr), "r"(rank));
    return r;
}
__device__ __forceinline__ void st_cluster_f32(uint32_t addr, float v) {
    asm volatile("st.shared::cluster.b32 [%0], %1;" :: "r"(addr), "r"(__float_as_uint(v)) : "memory");
}

// ---------------------------------------------------------------------------
// Stage 1: XW[l,g,n,:] = x[n,l,:] x1 W1[g] x2 W2[g] x3 W3[g]
// One CTA per (n,l); 512 threads; gates processed sequentially (t1/t2 reused).
// ---------------------------------------------------------------------------
__global__ __launch_bounds__(512) void xw_kernel(
    const float* __restrict__ x,
    const float* __restrict__ W1,   // (3,32,32)
    const float* __restrict__ W2,   // (3,16,16)
    const float* __restrict__ W3)   // (3,8,8)
{
    extern __shared__ float sm[];
    float* xs  = sm;              // 4096                x[a][b*8+c]
    float* t1  = xs + 4096;       // 32*T1P = 4352
    float* t2  = t1 + 4352;       // 32*T2DS = 4608
    float* w1t = t2 + 4608;       // 3072: w1t[a*96 + g*32 + d] = W1[g,d,a]
    float* w2t = w1t + 3072;      // 768:  w2t[g*256 + b*16 + e] = W2[g,e,b]
    float* w3s = w2t + 768;       // 192

    const int t = threadIdx.x;
    const int n = blockIdx.x;
    const int l = blockIdx.y;

    {
        const float4* xg4 = reinterpret_cast<const float4*>(x + ((size_t)n * L_STEPS + l) * HID);
        float4* xs4 = reinterpret_cast<float4*>(xs);
        for (int i = t; i < 1024; i += 512) xs4[i] = xg4[i];
    }
    for (int i = t; i < 3072; i += 512) {
        int g = i >> 10, rem = i & 1023, d = rem >> 5, a = rem & 31;
        w1t[a * 96 + g * 32 + d] = W1[i];
    }
    for (int i = t; i < 768; i += 512) {
        int g = i >> 8, rem = i & 255, e = rem >> 4, b = rem & 15;
        w2t[g * 256 + b * 16 + e] = W2[i];
    }
    for (int i = t; i < 192; i += 512) w3s[i] = W3[i];
    __syncthreads();

    const int warp = t >> 5, lane = t & 31;
    // phase1: warp -> 4 d-rows, lane -> 2 cols
    const int d0  = (warp & 7) * 4;
    const int bc0 = (warp >> 3) * 64 + lane * 2;
    // phase2: thread -> (d, e0..e0+3, c0..c0+1)
    const int dP2 = t >> 4;
    const int e0  = ((t >> 2) & 3) * 4;
    const int c0  = (t & 3) * 2;
    // phase3: thread = (d,e) pair
    const int p = t;

    for (int g = 0; g < 3; g++) {
        // ---- mode-1: t1[d][bc] = sum_a W1[g,d,a] * x[a][bc] ----
        float acc[4][2];
#pragma unroll
        for (int j = 0; j < 4; j++) { acc[j][0] = 0.f; acc[j][1] = 0.f; }
#pragma unroll
        for (int a = 0; a < 32; a++) {
            float2 x2 = *reinterpret_cast<const float2*>(&xs[a * 128 + bc0]);
            float4 wv = *reinterpret_cast<const float4*>(&w1t[a * 96 + g * 32 + d0]);
            acc[0][0] += wv.x * x2.x;  acc[0][1] += wv.x * x2.y;
            acc[1][0] += wv.y * x2.x;  acc[1][1] += wv.y * x2.y;
            acc[2][0] += wv.z * x2.x;  acc[2][1] += wv.z * x2.y;
            acc[3][0] += wv.w * x2.x;  acc[3][1] += wv.w * x2.y;
        }
#pragma unroll
        for (int j = 0; j < 4; j++)
            *reinterpret_cast<float2*>(&t1[(d0 + j) * T1P + bc0]) =
                make_float2(acc[j][0], acc[j][1]);
        __syncthreads();

        // ---- mode-2: t2[d][e*9+c] = sum_b W2[g,e,b] * t1[d][b*8+c] ----
        {
            const float* t1d = t1 + dP2 * T1P;
            const float* w2g = w2t + g * 256;
            float a00 = 0.f, a01 = 0.f, a10 = 0.f, a11 = 0.f;
            float a20 = 0.f, a21 = 0.f, a30 = 0.f, a31 = 0.f;
#pragma unroll
            for (int b = 0; b < 16; b++) {
                float2 tv = *reinterpret_cast<const float2*>(&t1d[b * 8 + c0]);
                float4 wv = *reinterpret_cast<const float4*>(&w2g[b * 16 + e0]);
                a00 += wv.x * tv.x;  a01 += wv.x * tv.y;
                a10 += wv.y * tv.x;  a11 += wv.y * tv.y;
                a20 += wv.z * tv.x;  a21 += wv.z * tv.y;
                a30 += wv.w * tv.x;  a31 += wv.w * tv.y;
            }
            float* t2d = t2 + dP2 * T2DS;
            t2d[(e0 + 0) * 9 + c0] = a00;  t2d[(e0 + 0) * 9 + c0 + 1] = a01;
            t2d[(e0 + 1) * 9 + c0] = a10;  t2d[(e0 + 1) * 9 + c0 + 1] = a11;
            t2d[(e0 + 2) * 9 + c0] = a20;  t2d[(e0 + 2) * 9 + c0 + 1] = a21;
            t2d[(e0 + 3) * 9 + c0] = a30;  t2d[(e0 + 3) * 9 + c0 + 1] = a31;
        }
        __syncthreads();

        // ---- mode-3: out[p*8+f] = sum_c W3[g,f,c] * t2[d][e*9+c] ----
        {
            const float* t2c = t2 + (p >> 4) * T2DS + (p & 15) * 9;
            float col[8];
#pragma unroll
            for (int c = 0; c < 8; c++) col[c] = t2c[c];
            const float* w3g = w3s + g * 64;
            float o[8];
#pragma unroll
            for (int f = 0; f < 8; f++) {
                float4 ua = *reinterpret_cast<const float4*>(&w3g[f * 8]);
                float4 ub = *reinterpret_cast<const float4*>(&w3g[f * 8 + 4]);
                o[f] = ua.x * col[0] + ua.y * col[1] + ua.z * col[2] + ua.w * col[3]
                     + ub.x * col[4] + ub.y * col[5] + ub.z * col[6] + ub.w * col[7];
            }
            float* outg = g_xw + (((size_t)l * 3 + g) * NB + n) * HID + p * 8;
            *reinterpret_cast<float4*>(outg)     = make_float4(o[0], o[1], o[2], o[3]);
            *reinterpret_cast<float4*>(outg + 4) = make_float4(o[4], o[5], o[6], o[7]);
        }
        __syncthreads();   // protect t1/t2 for next gate
    }
}

// ---------------------------------------------------------------------------
// Stage 2: GRU recurrence. Cluster of 2 CTAs per sample (128 CTAs, 512 thr).
// Each CTA owns d in [rank*16, rank*16+16); full h replicated & double-buffered;
// halves exchanged via DSMEM each step; ONE cluster barrier per step.
// ---------------------------------------------------------------------------
__global__ __launch_bounds__(512) __cluster_dims__(2, 1, 1)
void gru_kernel(
    const float* __restrict__ U1,   // (3,32,32)
    const float* __restrict__ U2,   // (3,16,16)
    const float* __restrict__ U3,   // (3,8,8)
    float* __restrict__ out)        // outs (N,L,4096) then h_last (N,4096)
{
    extern __shared__ float sm[];
    float* h0  = sm;                 // 4096
    float* h1  = h0 + 4096;          // 4096
    float* t1  = h1 + 4096;          // 48*T1P = 6528   rows r = g*16+dd
    float* t2  = t1 + 6528;          // 48*T2DS = 6912
    float* u1t = t2 + 6912;          // 1536: u1t[a*48 + g*16 + dd] = U1[g, rank*16+dd, a]
    float* w2t = u1t + 1536;         // 768:  w2t[g*256 + b*16 + e] = U2[g,e,b]
    float* u3s = w2t + 768;          // 192

    const int t    = threadIdx.x;
    const int n    = blockIdx.x >> 1;
    const int rank = blockIdx.x & 1;
    const int peer = rank ^ 1;

    for (int i = t; i < 4096; i += 512) h0[i] = 0.f;
    for (int i = t; i < 1536; i += 512) {
        int g = i >> 9, rem = i & 511, dd = rem >> 5, a = rem & 31;
        u1t[a * 48 + g * 16 + dd] = U1[((g * 32) + rank * 16 + dd) * 32 + a];
    }
    for (int i = t; i < 768; i += 512) {
        int g = i >> 8, rem = i & 255, e = rem >> 4, b = rem & 15;
        w2t[g * 256 + b * 16 + e] = U2[i];
    }
    for (int i = t; i < 192; i += 512) u3s[i] = U3[i];
    __syncthreads();

    const uint32_t h0a = smem_u32(h0);
    const uint32_t h1a = smem_u32(h1);

    const int warp = t >> 5, lane = t & 31;
    // phase1: warp -> 3 t1-rows (of 48), lane -> 4 cols
    const int r0  = warp * 3;
    const int bc0 = lane * 4;
    // phase2: thread -> (dd, e0..e0+3, single c)
    const int d2 = t >> 5;
    const int e0 = ((t >> 3) & 3) * 4;
    const int c1 = t & 7;
    // phase3: q = (dd,e) pair of this CTA's half; f0 = 4-element f group
    const int q   = t & 255;
    const int dd3 = q >> 4, e3 = q & 15;
    const int f0  = (t >> 8) * 4;
    const int gbase = ((rank * 16 + dd3) * 16 + e3) * 8 + f0;  // global hidden idx (4 elems)

    float* hc = h0;
    float* hn = h1;

    for (int l = 0; l < L_STEPS; l++) {
        // ---------- phase 1: t1[r][bc] = sum_a u1t[a][r] * hc[a*128+bc]
        float acc[3][4];
#pragma unroll
        for (int j = 0; j < 3; j++)
#pragma unroll
            for (int k = 0; k < 4; k++) acc[j][k] = 0.f;
#pragma unroll
        for (int a = 0; a < 32; a++) {
            float4 h4 = *reinterpret_cast<const float4*>(&hc[a * 128 + bc0]);
            float w0 = u1t[a * 48 + r0];
            float w1 = u1t[a * 48 + r0 + 1];
            float w2 = u1t[a * 48 + r0 + 2];
            acc[0][0] += w0 * h4.x; acc[0][1] += w0 * h4.y; acc[0][2] += w0 * h4.z; acc[0][3] += w0 * h4.w;
            acc[1][0] += w1 * h4.x; acc[1][1] += w1 * h4.y; acc[1][2] += w1 * h4.z; acc[1][3] += w1 * h4.w;
            acc[2][0] += w2 * h4.x; acc[2][1] += w2 * h4.y; acc[2][2] += w2 * h4.z; acc[2][3] += w2 * h4.w;
        }
#pragma unroll
        for (int j = 0; j < 3; j++)
            *reinterpret_cast<float4*>(&t1[(r0 + j) * T1P + bc0]) =
                make_float4(acc[j][0], acc[j][1], acc[j][2], acc[j][3]);

        // prefetch this step's XW (consumed in phase 3)
        float4 xf[3];
#pragma unroll
        for (int g = 0; g < 3; g++)
            xf[g] = *reinterpret_cast<const float4*>(
                g_xw + (((size_t)l * 3 + g) * NB + n) * HID + gbase);
        __syncthreads();

        // ---------- phase 2: t2[g,dd][e*9+c] = sum_b U2[g,e,b]*t1[g,dd][b*8+c]
#pragma unroll
        for (int g = 0; g < 3; g++) {
            const float* t1r = t1 + (g * 16 + d2) * T1P;
            const float* w2g = w2t + g * 256;
            float b0 = 0.f, b1 = 0.f, b2 = 0.f, b3 = 0.f;
#pragma unroll
            for (int b = 0; b < 16; b++) {
                float tv = t1r[b * 8 + c1];
                float4 wv = *reinterpret_cast<const float4*>(&w2g[b * 16 + e0]);
                b0 += wv.x * tv; b1 += wv.y * tv; b2 += wv.z * tv; b3 += wv.w * tv;
            }
            float* t2r = t2 + (g * 16 + d2) * T2DS;
            t2r[(e0 + 0) * 9 + c1] = b0;
            t2r[(e0 + 1) * 9 + c1] = b1;
            t2r[(e0 + 2) * 9 + c1] = b2;
            t2r[(e0 + 3) * 9 + c1] = b3;
        }
        __syncthreads();

        // ---------- phase 3: mode-3 + gate combine for 4 elements (gbase..+3)
        float hu[3][4];
#pragma unroll
        for (int g = 0; g < 3; g++) {
            const float* t2c = t2 + (g * 16 + dd3) * T2DS + e3 * 9;
            float col[8];
#pragma unroll
            for (int c = 0; c < 8; c++) col[c] = t2c[c];
            const float* u3g = u3s + g * 64;
#pragma unroll
            for (int j = 0; j < 4; j++) {
                float4 ua = *reinterpret_cast<const float4*>(&u3g[(f0 + j) * 8]);
                float4 ub = *reinterpret_cast<const float4*>(&u3g[(f0 + j) * 8 + 4]);
                hu[g][j] = ua.x * col[0] + ua.y * col[1] + ua.z * col[2] + ua.w * col[3]
                         + ub.x * col[4] + ub.y * col[5] + ub.z * col[6] + ub.w * col[7];
            }
        }
        float4 ho = *reinterpret_cast<const float4*>(&hc[gbase]);
        float hold[4] = {ho.x, ho.y, ho.z, ho.w};
        float xz[4] = {xf[0].x, xf[0].y, xf[0].z, xf[0].w};
        float xr[4] = {xf[1].x, xf[1].y, xf[1].z, xf[1].w};
        float xh[4] = {xf[2].x, xf[2].y, xf[2].z, xf[2].w};

        float res[4];
#pragma unroll
        for (int j = 0; j < 4; j++) {
            float z  = 1.f / (1.f + __expf(-(xz[j] + hu[0][j])));
            float r  = 1.f / (1.f + __expf(-(xr[j] + hu[1][j])));
            float ax = xh[j] + r * hu[2][j];
            float e2 = __expf(2.f * ax);
            float hh = 1.f - 2.f / (e2 + 1.f);
            res[j] = z * hold[j] + (1.f - z) * hh;
        }
        float4 r4 = make_float4(res[0], res[1], res[2], res[3]);
        *reinterpret_cast<float4*>(&hn[gbase]) = r4;

        // publish our half to peer's hn via DSMEM
        {
            uint32_t hna = (l & 1) ? h0a : h1a;       // address of hn buffer
            uint32_t ra = mapa_u32(hna + (uint32_t)gbase * 4u, (uint32_t)peer);
            st_cluster_f32(ra,      res[0]);
            st_cluster_f32(ra + 4,  res[1]);
            st_cluster_f32(ra + 8,  res[2]);
            st_cluster_f32(ra + 12, res[3]);
        }

        *reinterpret_cast<float4*>(out + ((size_t)n * L_STEPS + l) * HID + gbase) = r4;

        // one cluster barrier per step: peer's writes to hn become visible,
        // and nobody races ahead to overwrite the buffer we just read.
        asm volatile("barrier.cluster.arrive.aligned;" ::: "memory");
        asm volatile("barrier.cluster.wait.aligned;"   ::: "memory");

        float* tmp = hc; hc = hn; hn = tmp;
    }

    // h_last: each CTA writes its own half
    float* hl = out + (size_t)NB * L_STEPS * HID + (size_t)n * HID + rank * 2048;
    const float* hsrc = hc + rank * 2048;
    for (int i = t; i < 2048; i += 512) hl[i] = hsrc[i];
}

// ---------------------------------------------------------------------------
extern "C" void kernel_launch(void* const* d_in, const int* in_sizes, int n_in,
                              void* d_out, int out_size)
{
    const float* x  = (const float*)d_in[0];
    const float* W1 = (const float*)d_in[1];
    const float* W2 = (const float*)d_in[2];
    const float* W3 = (const float*)d_in[3];
    const float* U1 = (const float*)d_in[4];
    const float* U2 = (const float*)d_in[5];
    const float* U3 = (const float*)d_in[6];
    float* out = (float*)d_out;

    const int SMEM1 = (4096 + 4352 + 4608 + 3072 + 768 + 192) * (int)sizeof(float);
    const int SMEM2 = (4096 * 2 + 6528 + 6912 + 1536 + 768 + 192) * (int)sizeof(float);

    cudaFuncSetAttribute(xw_kernel,  cudaFuncAttributeMaxDynamicSharedMemorySize, SMEM1);
    cudaFuncSetAttribute(gru_kernel, cudaFuncAttributeMaxDynamicSharedMemorySize, SMEM2);

    dim3 grid1(NB, L_STEPS);
    xw_kernel<<<grid1, 512, SMEM1>>>(x, W1, W2, W3);
    gru_kernel<<<NB * 2, 512, SMEM2>>>(U1, U2, U3, out);
}

// round 6
// speedup vs baseline: 4.1730x; 1.1667x over previous
#include <cuda_runtime.h>
#include <math.h>
#include <cstdint>

typedef unsigned long long ull;

// Problem constants
#define L_STEPS 128
#define NB 64
#define HID 4096            // 32*16*8
#define T1P 136             // t1 row stride (words)
#define T2R 160             // t2 row stride (words); (e,c) -> e*10 + c

// XW scratch: (L, 3, N, 4096) fp32 = 402 MB.
__device__ float g_xw[(size_t)L_STEPS * 3 * NB * HID];

__device__ __forceinline__ void fma2(ull& acc, ull a, ull b) {
    asm("fma.rn.f32x2 %0, %1, %2, %0;" : "+l"(acc) : "l"(a), "l"(b));
}
__device__ __forceinline__ ull dup2(float x) {
    ull r; asm("mov.b64 %0, {%1, %1};" : "=l"(r) : "f"(x)); return r;
}
__device__ __forceinline__ ull pack2(float lo, float hi) {
    ull r; asm("mov.b64 %0, {%1, %2};" : "=l"(r) : "f"(lo), "f"(hi)); return r;
}
__device__ __forceinline__ uint32_t smem_u32(const void* p) {
    uint32_t a;
    asm("{ .reg .u64 t; cvta.to.shared.u64 t, %1; cvt.u32.u64 %0, t; }" : "=r"(a) : "l"(p));
    return a;
}
__device__ __forceinline__ uint32_t mapa_u32(uint32_t addr, uint32_t rank) {
    uint32_t r;
    asm("mapa.shared::cluster.u32 %0, %1, %2;" : "=r"(r) : "r"(addr), "r"(rank));
    return r;
}
__device__ __forceinline__ void st_cluster_b64(uint32_t addr, ull v) {
    asm volatile("st.shared::cluster.b64 [%0], %1;" :: "r"(addr), "l"(v) : "memory");
}

// ---------------------------------------------------------------------------
// Stage 1: XW[l,g,n,:] = x[n,l,:] x1 W1[g] x2 W2[g] x3 W3[g]
// One CTA per (n,l); 512 threads; gates sequential (t1/t2 reused).
// ---------------------------------------------------------------------------
__global__ __launch_bounds__(512) void xw_kernel(
    const float* __restrict__ x,
    const float* __restrict__ W1,   // (3,32,32)
    const float* __restrict__ W2,   // (3,16,16)
    const float* __restrict__ W3)   // (3,8,8)
{
    extern __shared__ float sm[];
    float* xs  = sm;              // 4096: x[a][b*8+c]
    float* t1  = xs + 4096;       // 32*T1P = 4352
    float* t2  = t1 + 4352;       // 32*T2R = 5120
    float* w1t = t2 + 5120;       // 3072: w1t[a*96 + g*32 + d] = W1[g,d,a]
    float* w2t = w1t + 3072;      // 768:  w2t[g*256 + b*16 + e] = W2[g,e,b]
    float* w3s = w2t + 768;       // 192

    const int t = threadIdx.x;
    const int n = blockIdx.x;
    const int l = blockIdx.y;

    {
        const float4* xg4 = reinterpret_cast<const float4*>(x + ((size_t)n * L_STEPS + l) * HID);
        float4* xs4 = reinterpret_cast<float4*>(xs);
        for (int i = t; i < 1024; i += 512) xs4[i] = xg4[i];
    }
    for (int i = t; i < 3072; i += 512) {
        int g = i >> 10, rem = i & 1023, d = rem >> 5, a = rem & 31;
        w1t[a * 96 + g * 32 + d] = W1[i];
    }
    for (int i = t; i < 768; i += 512) {
        int g = i >> 8, rem = i & 255, e = rem >> 4, b = rem & 15;
        w2t[g * 256 + b * 16 + e] = W2[i];
    }
    for (int i = t; i < 192; i += 512) w3s[i] = W3[i];
    __syncthreads();

    const int warp = t >> 5, lane = t & 31;
    // phase1: warp -> 4 d-rows, lane -> col pair
    const int d0  = (warp & 7) * 4;
    const int bc0 = (warp >> 3) * 64 + lane * 2;
    // phase2: thread -> (d, e0..e0+3, col pair c0)
    const int dP2 = t >> 4;
    const int e0  = ((t >> 2) & 3) * 4;
    const int c0  = (t & 3) * 2;
    // phase3: thread = (d,e) pair
    const int p = t;

    for (int g = 0; g < 3; g++) {
        // ---- mode-1 (f32x2): t1[d][bc] = sum_a W1[g,d,a] * x[a][bc] ----
        ull acc2[4] = {0, 0, 0, 0};
#pragma unroll
        for (int a = 0; a < 32; a++) {
            ull x2 = *reinterpret_cast<const ull*>(&xs[a * 128 + bc0]);
            float4 wv = *reinterpret_cast<const float4*>(&w1t[a * 96 + g * 32 + d0]);
            fma2(acc2[0], dup2(wv.x), x2);
            fma2(acc2[1], dup2(wv.y), x2);
            fma2(acc2[2], dup2(wv.z), x2);
            fma2(acc2[3], dup2(wv.w), x2);
        }
#pragma unroll
        for (int j = 0; j < 4; j++)
            *reinterpret_cast<ull*>(&t1[(d0 + j) * T1P + bc0]) = acc2[j];
        __syncthreads();

        // ---- mode-2 (f32x2): t2[d][e*10+c] = sum_b W2[g,e,b] * t1[d][b*8+c] ----
        {
            const float* t1d = t1 + dP2 * T1P;
            const float* w2g = w2t + g * 256;
            ull a0 = 0, a1 = 0, a2 = 0, a3 = 0;
#pragma unroll
            for (int b = 0; b < 16; b++) {
                ull tv = *reinterpret_cast<const ull*>(&t1d[b * 8 + c0]);
                float4 wv = *reinterpret_cast<const float4*>(&w2g[b * 16 + e0]);
                fma2(a0, dup2(wv.x), tv);
                fma2(a1, dup2(wv.y), tv);
                fma2(a2, dup2(wv.z), tv);
                fma2(a3, dup2(wv.w), tv);
            }
            float* t2d = t2 + dP2 * T2R;
            *reinterpret_cast<ull*>(&t2d[(e0 + 0) * 10 + c0]) = a0;
            *reinterpret_cast<ull*>(&t2d[(e0 + 1) * 10 + c0]) = a1;
            *reinterpret_cast<ull*>(&t2d[(e0 + 2) * 10 + c0]) = a2;
            *reinterpret_cast<ull*>(&t2d[(e0 + 3) * 10 + c0]) = a3;
        }
        __syncthreads();

        // ---- mode-3: out[p*8+f] = sum_c W3[g,f,c] * t2[d][e*10+c] ----
        {
            const float* t2c = t2 + (p >> 4) * T2R + (p & 15) * 10;
            float col[8];
#pragma unroll
            for (int c = 0; c < 8; c++) col[c] = t2c[c];
            const float* w3g = w3s + g * 64;
            float o[8];
#pragma unroll
            for (int f = 0; f < 8; f++) {
                float4 ua = *reinterpret_cast<const float4*>(&w3g[f * 8]);
                float4 ub = *reinterpret_cast<const float4*>(&w3g[f * 8 + 4]);
                o[f] = ua.x * col[0] + ua.y * col[1] + ua.z * col[2] + ua.w * col[3]
                     + ub.x * col[4] + ub.y * col[5] + ub.z * col[6] + ub.w * col[7];
            }
            float* outg = g_xw + (((size_t)l * 3 + g) * NB + n) * HID + p * 8;
            *reinterpret_cast<float4*>(outg)     = make_float4(o[0], o[1], o[2], o[3]);
            *reinterpret_cast<float4*>(outg + 4) = make_float4(o[4], o[5], o[6], o[7]);
        }
        __syncthreads();
    }
}

// ---------------------------------------------------------------------------
// Stage 2: GRU recurrence. Cluster of 2 CTAs per sample (128 CTAs, 512 thr).
// CTA owns d in [rank*16, rank*16+16); full h replicated, double-buffered;
// halves exchanged via DSMEM; warp-aligned t2 dataflow (syncwarp only).
// ---------------------------------------------------------------------------
__global__ __launch_bounds__(512) __cluster_dims__(2, 1, 1)
void gru_kernel(
    const float* __restrict__ U1,   // (3,32,32)
    const float* __restrict__ U2,   // (3,16,16)
    const float* __restrict__ U3,   // (3,8,8)
    float* __restrict__ out)        // outs (N,L,4096) then h_last (N,4096)
{
    extern __shared__ float sm[];
    float* h0  = sm;                 // 4096
    float* h1  = h0 + 4096;          // 4096
    float* t1  = h1 + 4096;          // 48*T1P = 6528   rows r = g*16+dd
    float* t2  = t1 + 6528;          // 48*T2R = 7680
    float* u1t = t2 + 7680;          // 1536: u1t[a*48 + g*16 + dd] = U1[g, rank*16+dd, a]
    float* w2t = u1t + 1536;         // 768:  w2t[g*256 + b*16 + e] = U2[g,e,b]
    float* u3s = w2t + 768;          // 192

    const int t    = threadIdx.x;
    const int n    = blockIdx.x >> 1;
    const int rank = blockIdx.x & 1;
    const int peer = rank ^ 1;

    for (int i = t; i < 4096; i += 512) h0[i] = 0.f;
    for (int i = t; i < 1536; i += 512) {
        int g = i >> 9, rem = i & 511, dd = rem >> 5, a = rem & 31;
        u1t[a * 48 + g * 16 + dd] = U1[((g * 32) + rank * 16 + dd) * 32 + a];
    }
    for (int i = t; i < 768; i += 512) {
        int g = i >> 8, rem = i & 255, e = rem >> 4, b = rem & 15;
        w2t[g * 256 + b * 16 + e] = U2[i];
    }
    for (int i = t; i < 192; i += 512) u3s[i] = U3[i];
    __syncthreads();

    const uint32_t h0a = smem_u32(h0);
    const uint32_t h1a = smem_u32(h1);

    const int warp = t >> 5, lane = t & 31;
    // phase1 (warps 0..11): r0 = warp*4 rows, lane -> 4 cols
    const int r0  = warp * 4;
    const int bc0 = lane * 4;
    // phase2: warp w -> dd = w; lane -> (e20, e20+1) x col-pair cp2
    const int e20 = (lane >> 2) * 2;
    const int cp2 = (lane & 3) * 2;
    // phase3: warp w -> dd = w; lane -> (e3, f0..f0+3)
    const int e3 = lane >> 1;
    const int f0 = (lane & 1) * 4;
    const int gbase = ((rank * 16 + warp) * 16 + e3) * 8 + f0;  // 4 global hidden elems

    float* hc = h0;
    float* hn = h1;

    for (int l = 0; l < L_STEPS; l++) {
        // XW prefetch for phase 3 (all warps) — overlaps with phase 1 compute
        float4 xf[3];
#pragma unroll
        for (int g = 0; g < 3; g++)
            xf[g] = *reinterpret_cast<const float4*>(
                g_xw + (((size_t)l * 3 + g) * NB + n) * HID + gbase);

        // ---------- phase 1 (warps 0-11): t1[r][bc] = sum_a u1t[a][r]*hc[a*128+bc]
        if (warp < 12) {
            ull acc2[4][2];
#pragma unroll
            for (int j = 0; j < 4; j++) { acc2[j][0] = 0; acc2[j][1] = 0; }
#pragma unroll
            for (int a = 0; a < 32; a++) {
                ulonglong2 hv = *reinterpret_cast<const ulonglong2*>(&hc[a * 128 + bc0]);
                float4 wv = *reinterpret_cast<const float4*>(&u1t[a * 48 + r0]);
                ull w0 = dup2(wv.x), w1 = dup2(wv.y), w2 = dup2(wv.z), w3 = dup2(wv.w);
                fma2(acc2[0][0], w0, hv.x);  fma2(acc2[0][1], w0, hv.y);
                fma2(acc2[1][0], w1, hv.x);  fma2(acc2[1][1], w1, hv.y);
                fma2(acc2[2][0], w2, hv.x);  fma2(acc2[2][1], w2, hv.y);
                fma2(acc2[3][0], w3, hv.x);  fma2(acc2[3][1], w3, hv.y);
            }
#pragma unroll
            for (int j = 0; j < 4; j++) {
                ulonglong2 st; st.x = acc2[j][0]; st.y = acc2[j][1];
                *reinterpret_cast<ulonglong2*>(&t1[(r0 + j) * T1P + bc0]) = st;
            }
        }
        __syncthreads();

        // ---------- phase 2: warp w computes t2 rows (g,dd=w), all e,c
#pragma unroll
        for (int g = 0; g < 3; g++) {
            const float* t1r = t1 + (g * 16 + warp) * T1P;
            const float* w2g = w2t + g * 256;
            ull a0 = 0, a1 = 0;
#pragma unroll
            for (int b = 0; b < 16; b++) {
                ull tv = *reinterpret_cast<const ull*>(&t1r[b * 8 + cp2]);
                float2 wv = *reinterpret_cast<const float2*>(&w2g[b * 16 + e20]);
                fma2(a0, dup2(wv.x), tv);
                fma2(a1, dup2(wv.y), tv);
            }
            float* t2r = t2 + (g * 16 + warp) * T2R;
            *reinterpret_cast<ull*>(&t2r[(e20 + 0) * 10 + cp2]) = a0;
            *reinterpret_cast<ull*>(&t2r[(e20 + 1) * 10 + cp2]) = a1;
        }
        __syncwarp();   // same warp produced exactly the t2 rows phase 3 reads

        // ---------- phase 3: mode-3 + gate combine for 4 elements (gbase..+3)
        float hu[3][4];
#pragma unroll
        for (int g = 0; g < 3; g++) {
            const float* t2c = t2 + (g * 16 + warp) * T2R + e3 * 10;
            float col[8];
#pragma unroll
            for (int k = 0; k < 4; k++) {
                float2 v = *reinterpret_cast<const float2*>(&t2c[k * 2]);
                col[2 * k] = v.x;  col[2 * k + 1] = v.y;
            }
            const float* u3g = u3s + g * 64;
#pragma unroll
            for (int j = 0; j < 4; j++) {
                float4 ua = *reinterpret_cast<const float4*>(&u3g[(f0 + j) * 8]);
                float4 ub = *reinterpret_cast<const float4*>(&u3g[(f0 + j) * 8 + 4]);
                hu[g][j] = ua.x * col[0] + ua.y * col[1] + ua.z * col[2] + ua.w * col[3]
                         + ub.x * col[4] + ub.y * col[5] + ub.z * col[6] + ub.w * col[7];
            }
        }
        float4 ho = *reinterpret_cast<const float4*>(&hc[gbase]);
        float hold[4] = {ho.x, ho.y, ho.z, ho.w};
        float xz[4] = {xf[0].x, xf[0].y, xf[0].z, xf[0].w};
        float xr[4] = {xf[1].x, xf[1].y, xf[1].z, xf[1].w};
        float xh[4] = {xf[2].x, xf[2].y, xf[2].z, xf[2].w};

        float res[4];
#pragma unroll
        for (int j = 0; j < 4; j++) {
            float z  = 1.f / (1.f + __expf(-(xz[j] + hu[0][j])));
            float r  = 1.f / (1.f + __expf(-(xr[j] + hu[1][j])));
            float ax = xh[j] + r * hu[2][j];
            float e2 = __expf(2.f * ax);
            float hh = 1.f - 2.f / (e2 + 1.f);      // tanh, NaN-safe
            res[j] = z * hold[j] + (1.f - z) * hh;
        }
        float4 r4 = make_float4(res[0], res[1], res[2], res[3]);
        *reinterpret_cast<float4*>(&hn[gbase]) = r4;

        // publish our half to peer's hn via DSMEM (2x b64)
        {
            uint32_t hna = (l & 1) ? h0a : h1a;
            uint32_t ra = mapa_u32(hna + (uint32_t)gbase * 4u, (uint32_t)peer);
            st_cluster_b64(ra,     pack2(res[0], res[1]));
            st_cluster_b64(ra + 8, pack2(res[2], res[3]));
        }

        // split cluster barrier: hide STG + barrier latency
        asm volatile("barrier.cluster.arrive.aligned;" ::: "memory");
        *reinterpret_cast<float4*>(out + ((size_t)n * L_STEPS + l) * HID + gbase) = r4;
        asm volatile("barrier.cluster.wait.aligned;"   ::: "memory");

        float* tmp = hc; hc = hn; hn = tmp;
    }

    // h_last: each CTA writes its own half
    float* hl = out + (size_t)NB * L_STEPS * HID + (size_t)n * HID + rank * 2048;
    const float* hsrc = hc + rank * 2048;
    for (int i = t; i < 2048; i += 512) hl[i] = hsrc[i];
}

// ---------------------------------------------------------------------------
extern "C" void kernel_launch(void* const* d_in, const int* in_sizes, int n_in,
                              void* d_out, int out_size)
{
    const float* x  = (const float*)d_in[0];
    const float* W1 = (const float*)d_in[1];
    const float* W2 = (const float*)d_in[2];
    const float* W3 = (const float*)d_in[3];
    const float* U1 = (const float*)d_in[4];
    const float* U2 = (const float*)d_in[5];
    const float* U3 = (const float*)d_in[6];
    float* out = (float*)d_out;

    const int SMEM1 = (4096 + 4352 + 5120 + 3072 + 768 + 192) * (int)sizeof(float);
    const int SMEM2 = (4096 * 2 + 6528 + 7680 + 1536 + 768 + 192) * (int)sizeof(float);

    cudaFuncSetAttribute(xw_kernel,  cudaFuncAttributeMaxDynamicSharedMemorySize, SMEM1);
    cudaFuncSetAttribute(gru_kernel, cudaFuncAttributeMaxDynamicSharedMemorySize, SMEM2);

    dim3 grid1(NB, L_STEPS);
    xw_kernel<<<grid1, 512, SMEM1>>>(x, W1, W2, W3);
    gru_kernel<<<NB * 2, 512, SMEM2>>>(U1, U2, U3, out);
}

// round 7
// speedup vs baseline: 4.1838x; 1.0026x over previous
#include <cuda_runtime.h>
#include <math.h>
#include <cstdint>

typedef unsigned long long ull;

// Problem constants
#define L_STEPS 128
#define NB 64
#define HID 4096            // 32*16*8
#define T1S 128             // t1 row stride (contiguous; p2 reads are warp-broadcast)
#define T2R 160             // t2 row stride; (e,c) -> e*10 + c  (b64-aligned, conflict-free)

// XW scratch: (L, 3, N, 4096) fp32 = 402 MB.
__device__ float g_xw[(size_t)L_STEPS * 3 * NB * HID];

__device__ __forceinline__ void fma2(ull& acc, ull a, ull b) {
    asm("fma.rn.f32x2 %0, %1, %2, %0;" : "+l"(acc) : "l"(a), "l"(b));
}
__device__ __forceinline__ ull dup2(float x) {
    ull r; asm("mov.b64 %0, {%1, %1};" : "=l"(r) : "f"(x)); return r;
}
__device__ __forceinline__ ull pack2(float lo, float hi) {
    ull r; asm("mov.b64 %0, {%1, %2};" : "=l"(r) : "f"(lo), "f"(hi)); return r;
}
__device__ __forceinline__ uint32_t smem_u32(const void* p) {
    uint32_t a;
    asm("{ .reg .u64 t; cvta.to.shared.u64 t, %1; cvt.u32.u64 %0, t; }" : "=r"(a) : "l"(p));
    return a;
}
__device__ __forceinline__ uint32_t mapa_u32(uint32_t addr, uint32_t rank) {
    uint32_t r;
    asm("mapa.shared::cluster.u32 %0, %1, %2;" : "=r"(r) : "r"(addr), "r"(rank));
    return r;
}
__device__ __forceinline__ void st_cluster_b64(uint32_t addr, ull v) {
    asm volatile("st.shared::cluster.b64 [%0], %1;" :: "r"(addr), "l"(v) : "memory");
}

// ---------------------------------------------------------------------------
// Stage 1: XW[l,g,n,:] = x[n,l,:] x1 W1[g] x2 W2[g] x3 W3[g]
// One CTA per (n,l); 512 threads. All 96 rows (3 gates x 32 d) in ONE pass:
// warp w (0..11) owns rows 8w..8w+7 through fused phase1+phase2 (syncwarp only),
// then one __syncthreads, then phase 3.
// ---------------------------------------------------------------------------
__global__ __launch_bounds__(512) void xw_kernel(
    const float* __restrict__ x,
    const float* __restrict__ W1,   // (3,32,32)
    const float* __restrict__ W2,   // (3,16,16)
    const float* __restrict__ W3)   // (3,8,8)
{
    extern __shared__ float sm[];
    float* xs  = sm;              // 4096: x[a][b*8+c]
    float* t1  = xs + 4096;       // 96*T1S = 12288, rows r = g*32+d
    float* t2  = t1 + 12288;      // 96*T2R = 15360
    float* w1t = t2 + 15360;      // 3072: w1t[a*96 + g*32 + d] = W1[g,d,a]
    float* w2t = w1t + 3072;      // 768:  w2t[g*256 + b*16 + e] = W2[g,e,b]
    float* w3s = w2t + 768;       // 192

    const int t = threadIdx.x;
    const int n = blockIdx.x;
    const int l = blockIdx.y;

    {
        const float4* xg4 = reinterpret_cast<const float4*>(x + ((size_t)n * L_STEPS + l) * HID);
        float4* xs4 = reinterpret_cast<float4*>(xs);
        for (int i = t; i < 1024; i += 512) xs4[i] = xg4[i];
    }
    for (int i = t; i < 3072; i += 512) {
        int g = i >> 10, rem = i & 1023, d = rem >> 5, a = rem & 31;
        w1t[a * 96 + g * 32 + d] = W1[i];
    }
    for (int i = t; i < 768; i += 512) {
        int g = i >> 8, rem = i & 255, e = rem >> 4, b = rem & 15;
        w2t[g * 256 + b * 16 + e] = W2[i];
    }
    for (int i = t; i < 192; i += 512) w3s[i] = W3[i];
    __syncthreads();

    const int warp = t >> 5, lane = t & 31;
    const int r0  = warp * 8;           // 8 rows per warp (warps 0..11)
    const int bc0 = lane * 4;           // 4 cols per lane
    // phase2 lane mapping: e = lane>>1, c-half = lane&1 (4 c's)
    const int e2 = lane >> 1;
    const int c4 = (lane & 1) * 4;

    if (warp < 12) {
        // ---- fused phase 1: t1[r][bc] = sum_a W1t[a][r] * x[a][bc] ----
        ull acc2[8][2];
#pragma unroll
        for (int j = 0; j < 8; j++) { acc2[j][0] = 0; acc2[j][1] = 0; }
#pragma unroll
        for (int a = 0; a < 32; a++) {
            ulonglong2 xv = *reinterpret_cast<const ulonglong2*>(&xs[a * 128 + bc0]);
            float4 wa = *reinterpret_cast<const float4*>(&w1t[a * 96 + r0]);
            float4 wb = *reinterpret_cast<const float4*>(&w1t[a * 96 + r0 + 4]);
            ull w0 = dup2(wa.x), w1 = dup2(wa.y), w2 = dup2(wa.z), w3 = dup2(wa.w);
            ull w4 = dup2(wb.x), w5 = dup2(wb.y), w6 = dup2(wb.z), w7 = dup2(wb.w);
            fma2(acc2[0][0], w0, xv.x);  fma2(acc2[0][1], w0, xv.y);
            fma2(acc2[1][0], w1, xv.x);  fma2(acc2[1][1], w1, xv.y);
            fma2(acc2[2][0], w2, xv.x);  fma2(acc2[2][1], w2, xv.y);
            fma2(acc2[3][0], w3, xv.x);  fma2(acc2[3][1], w3, xv.y);
            fma2(acc2[4][0], w4, xv.x);  fma2(acc2[4][1], w4, xv.y);
            fma2(acc2[5][0], w5, xv.x);  fma2(acc2[5][1], w5, xv.y);
            fma2(acc2[6][0], w6, xv.x);  fma2(acc2[6][1], w6, xv.y);
            fma2(acc2[7][0], w7, xv.x);  fma2(acc2[7][1], w7, xv.y);
        }
#pragma unroll
        for (int j = 0; j < 8; j++) {
            ulonglong2 st; st.x = acc2[j][0]; st.y = acc2[j][1];
            *reinterpret_cast<ulonglong2*>(&t1[(r0 + j) * T1S + bc0]) = st;
        }
        __syncwarp();

        // ---- fused phase 2: t2[r][e*10+c] = sum_b W2[g,e,b] * t1[r][b*8+c] ----
        const int g = warp >> 2;
        const float* w2g = w2t + g * 256;
        ull a2[8][2];
#pragma unroll
        for (int j = 0; j < 8; j++) { a2[j][0] = 0; a2[j][1] = 0; }
#pragma unroll
        for (int b = 0; b < 16; b++) {
            ull wd = dup2(w2g[b * 16 + e2]);
#pragma unroll
            for (int j = 0; j < 8; j++) {
                ulonglong2 tv = *reinterpret_cast<const ulonglong2*>(
                    &t1[(r0 + j) * T1S + b * 8 + c4]);
                fma2(a2[j][0], wd, tv.x);
                fma2(a2[j][1], wd, tv.y);
            }
        }
#pragma unroll
        for (int j = 0; j < 8; j++) {
            float* t2r = t2 + (r0 + j) * T2R + e2 * 10 + c4;
            *reinterpret_cast<ull*>(t2r)     = a2[j][0];
            *reinterpret_cast<ull*>(t2r + 2) = a2[j][1];
        }
    }
    __syncthreads();

    // ---- phase 3: out[(d*16+e)*8+f] = sum_c W3[g,f,c] * t2[g*32+d][e*10+c] ----
    {
        const int d = t >> 4, e = t & 15;
#pragma unroll
        for (int g = 0; g < 3; g++) {
            const float* t2c = t2 + (g * 32 + d) * T2R + e * 10;
            float col[8];
#pragma unroll
            for (int k = 0; k < 4; k++) {
                float2 v = *reinterpret_cast<const float2*>(&t2c[k * 2]);
                col[2 * k] = v.x;  col[2 * k + 1] = v.y;
            }
            const float* w3g = w3s + g * 64;
            float o[8];
#pragma unroll
            for (int f = 0; f < 8; f++) {
                float4 ua = *reinterpret_cast<const float4*>(&w3g[f * 8]);
                float4 ub = *reinterpret_cast<const float4*>(&w3g[f * 8 + 4]);
                o[f] = ua.x * col[0] + ua.y * col[1] + ua.z * col[2] + ua.w * col[3]
                     + ub.x * col[4] + ub.y * col[5] + ub.z * col[6] + ub.w * col[7];
            }
            float* outg = g_xw + (((size_t)l * 3 + g) * NB + n) * HID + t * 8;
            *reinterpret_cast<float4*>(outg)     = make_float4(o[0], o[1], o[2], o[3]);
            *reinterpret_cast<float4*>(outg + 4) = make_float4(o[4], o[5], o[6], o[7]);
        }
    }
}

// ---------------------------------------------------------------------------
// Stage 2: GRU recurrence. Cluster of 2 CTAs per sample (128 CTAs, 512 thr).
// CTA owns d in [rank*16, rank*16+16). Fused phase1+phase2 per warp
// (warp w owns t1 rows 4w..4w+3; syncwarp only), one __syncthreads, phase 3,
// DSMEM half-exchange, one cluster barrier per step.
// ---------------------------------------------------------------------------
__global__ __launch_bounds__(512) __cluster_dims__(2, 1, 1)
void gru_kernel(
    const float* __restrict__ U1,   // (3,32,32)
    const float* __restrict__ U2,   // (3,16,16)
    const float* __restrict__ U3,   // (3,8,8)
    float* __restrict__ out)        // outs (N,L,4096) then h_last (N,4096)
{
    extern __shared__ float sm[];
    float* h0  = sm;                 // 4096
    float* h1  = h0 + 4096;          // 4096
    float* t1  = h1 + 4096;          // 48*T1S = 6144   rows r = g*16+dd
    float* t2  = t1 + 6144;          // 48*T2R = 7680
    float* u1t = t2 + 7680;          // 1536: u1t[a*48 + g*16 + dd] = U1[g, rank*16+dd, a]
    float* w2t = u1t + 1536;         // 768:  w2t[g*256 + b*16 + e] = U2[g,e,b]
    float* u3s = w2t + 768;          // 192

    const int t    = threadIdx.x;
    const int n    = blockIdx.x >> 1;
    const int rank = blockIdx.x & 1;
    const int peer = rank ^ 1;

    for (int i = t; i < 4096; i += 512) h0[i] = 0.f;
    for (int i = t; i < 1536; i += 512) {
        int g = i >> 9, rem = i & 511, dd = rem >> 5, a = rem & 31;
        u1t[a * 48 + g * 16 + dd] = U1[((g * 32) + rank * 16 + dd) * 32 + a];
    }
    for (int i = t; i < 768; i += 512) {
        int g = i >> 8, rem = i & 255, e = rem >> 4, b = rem & 15;
        w2t[g * 256 + b * 16 + e] = U2[i];
    }
    for (int i = t; i < 192; i += 512) u3s[i] = U3[i];
    __syncthreads();

    const uint32_t h0a = smem_u32(h0);
    const uint32_t h1a = smem_u32(h1);

    const int warp = t >> 5, lane = t & 31;
    // fused p1+p2 (warps 0..11): r0 = 4 rows; lane -> 4 cols (p1) / (e,c-half) (p2)
    const int r0  = warp * 4;
    const int bc0 = lane * 4;
    const int e2  = lane >> 1;
    const int c4  = (lane & 1) * 4;
    // phase3: warp = dd; lane -> (e3, f0..f0+3)
    const int e3 = lane >> 1;
    const int f0 = (lane & 1) * 4;
    const int gbase = ((rank * 16 + warp) * 16 + e3) * 8 + f0;  // 4 global hidden elems

    float* hc = h0;
    float* hn = h1;

    for (int l = 0; l < L_STEPS; l++) {
        // XW prefetch for phase 3 — issued first, hidden under fused p1+p2
        float4 xf[3];
#pragma unroll
        for (int g = 0; g < 3; g++)
            xf[g] = *reinterpret_cast<const float4*>(
                g_xw + (((size_t)l * 3 + g) * NB + n) * HID + gbase);

        if (warp < 12) {
            // ---- fused phase 1: t1[r][bc] = sum_a u1t[a][r]*hc[a*128+bc] ----
            ull acc2[4][2];
#pragma unroll
            for (int j = 0; j < 4; j++) { acc2[j][0] = 0; acc2[j][1] = 0; }
#pragma unroll
            for (int a = 0; a < 32; a++) {
                ulonglong2 hv = *reinterpret_cast<const ulonglong2*>(&hc[a * 128 + bc0]);
                float4 wv = *reinterpret_cast<const float4*>(&u1t[a * 48 + r0]);
                ull w0 = dup2(wv.x), w1 = dup2(wv.y), w2 = dup2(wv.z), w3 = dup2(wv.w);
                fma2(acc2[0][0], w0, hv.x);  fma2(acc2[0][1], w0, hv.y);
                fma2(acc2[1][0], w1, hv.x);  fma2(acc2[1][1], w1, hv.y);
                fma2(acc2[2][0], w2, hv.x);  fma2(acc2[2][1], w2, hv.y);
                fma2(acc2[3][0], w3, hv.x);  fma2(acc2[3][1], w3, hv.y);
            }
#pragma unroll
            for (int j = 0; j < 4; j++) {
                ulonglong2 st; st.x = acc2[j][0]; st.y = acc2[j][1];
                *reinterpret_cast<ulonglong2*>(&t1[(r0 + j) * T1S + bc0]) = st;
            }
            __syncwarp();

            // ---- fused phase 2: t2[r][e*10+c] = sum_b U2[g,e,b]*t1[r][b*8+c] ----
            const int g = warp >> 2;
            const float* w2g = w2t + g * 256;
            ull a2[4][2];
#pragma unroll
            for (int j = 0; j < 4; j++) { a2[j][0] = 0; a2[j][1] = 0; }
#pragma unroll
            for (int b = 0; b < 16; b++) {
                ull wd = dup2(w2g[b * 16 + e2]);
#pragma unroll
                for (int j = 0; j < 4; j++) {
                    ulonglong2 tv = *reinterpret_cast<const ulonglong2*>(
                        &t1[(r0 + j) * T1S + b * 8 + c4]);
                    fma2(a2[j][0], wd, tv.x);
                    fma2(a2[j][1], wd, tv.y);
                }
            }
#pragma unroll
            for (int j = 0; j < 4; j++) {
                float* t2r = t2 + (r0 + j) * T2R + e2 * 10 + c4;
                *reinterpret_cast<ull*>(t2r)     = a2[j][0];
                *reinterpret_cast<ull*>(t2r + 2) = a2[j][1];
            }
        }
        __syncthreads();

        // ---- phase 3: mode-3 + gate combine for 4 elements (gbase..+3) ----
        float hu[3][4];
#pragma unroll
        for (int g = 0; g < 3; g++) {
            const float* t2c = t2 + (g * 16 + warp) * T2R + e3 * 10;
            float col[8];
#pragma unroll
            for (int k = 0; k < 4; k++) {
                float2 v = *reinterpret_cast<const float2*>(&t2c[k * 2]);
                col[2 * k] = v.x;  col[2 * k + 1] = v.y;
            }
            const float* u3g = u3s + g * 64;
#pragma unroll
            for (int j = 0; j < 4; j++) {
                float4 ua = *reinterpret_cast<const float4*>(&u3g[(f0 + j) * 8]);
                float4 ub = *reinterpret_cast<const float4*>(&u3g[(f0 + j) * 8 + 4]);
                hu[g][j] = ua.x * col[0] + ua.y * col[1] + ua.z * col[2] + ua.w * col[3]
                         + ub.x * col[4] + ub.y * col[5] + ub.z * col[6] + ub.w * col[7];
            }
        }
        float4 ho = *reinterpret_cast<const float4*>(&hc[gbase]);
        float hold[4] = {ho.x, ho.y, ho.z, ho.w};
        float xz[4] = {xf[0].x, xf[0].y, xf[0].z, xf[0].w};
        float xr[4] = {xf[1].x, xf[1].y, xf[1].z, xf[1].w};
        float xh[4] = {xf[2].x, xf[2].y, xf[2].z, xf[2].w};

        float res[4];
#pragma unroll
        for (int j = 0; j < 4; j++) {
            float z  = 1.f / (1.f + __expf(-(xz[j] + hu[0][j])));
            float r  = 1.f / (1.f + __expf(-(xr[j] + hu[1][j])));
            float ax = xh[j] + r * hu[2][j];
            float e2x = __expf(2.f * ax);
            float hh = 1.f - 2.f / (e2x + 1.f);      // tanh, NaN-safe
            res[j] = z * hold[j] + (1.f - z) * hh;
        }
        float4 r4 = make_float4(res[0], res[1], res[2], res[3]);
        *reinterpret_cast<float4*>(&hn[gbase]) = r4;

        // publish our half to peer's hn via DSMEM (2x b64)
        {
            uint32_t hna = (l & 1) ? h0a : h1a;
            uint32_t ra = mapa_u32(hna + (uint32_t)gbase * 4u, (uint32_t)peer);
            st_cluster_b64(ra,     pack2(res[0], res[1]));
            st_cluster_b64(ra + 8, pack2(res[2], res[3]));
        }

        // split cluster barrier: hide STG + barrier latency
        asm volatile("barrier.cluster.arrive.aligned;" ::: "memory");
        *reinterpret_cast<float4*>(out + ((size_t)n * L_STEPS + l) * HID + gbase) = r4;
        asm volatile("barrier.cluster.wait.aligned;"   ::: "memory");

        float* tmp = hc; hc = hn; hn = tmp;
    }

    // h_last: each CTA writes its own half
    float* hl = out + (size_t)NB * L_STEPS * HID + (size_t)n * HID + rank * 2048;
    const float* hsrc = hc + rank * 2048;
    for (int i = t; i < 2048; i += 512) hl[i] = hsrc[i];
}

// ---------------------------------------------------------------------------
extern "C" void kernel_launch(void* const* d_in, const int* in_sizes, int n_in,
                              void* d_out, int out_size)
{
    const float* x  = (const float*)d_in[0];
    const float* W1 = (const float*)d_in[1];
    const float* W2 = (const float*)d_in[2];
    const float* W3 = (const float*)d_in[3];
    const float* U1 = (const float*)d_in[4];
    const float* U2 = (const float*)d_in[5];
    const float* U3 = (const float*)d_in[6];
    float* out = (float*)d_out;

    const int SMEM1 = (4096 + 12288 + 15360 + 3072 + 768 + 192) * (int)sizeof(float);
    const int SMEM2 = (4096 * 2 + 6144 + 7680 + 1536 + 768 + 192) * (int)sizeof(float);

    cudaFuncSetAttribute(xw_kernel,  cudaFuncAttributeMaxDynamicSharedMemorySize, SMEM1);
    cudaFuncSetAttribute(gru_kernel, cudaFuncAttributeMaxDynamicSharedMemorySize, SMEM2);

    dim3 grid1(NB, L_STEPS);
    xw_kernel<<<grid1, 512, SMEM1>>>(x, W1, W2, W3);
    gru_kernel<<<NB * 2, 512, SMEM2>>>(U1, U2, U3, out);
}